// round 14
// baseline (speedup 1.0000x reference)
#include <cuda_runtime.h>
#include <cuda_fp16.h>
#include <stdint.h>

#define B_ 4
#define L_ 4096
#define D_ 512
#define M_ (B_*L_)

// ---------------- device scratch ---------------------------------------------
__device__ __half g_x16[(size_t)M_*D_];
__device__ __half g_WqT[D_*D_], g_WkT[D_*D_];
__device__ __half g_H[D_*D_];
__device__ __half g_Y[(size_t)M_*D_];
__device__ float g_colw[B_*L_];
__device__ float g_t[B_*D_];

// ---------------- helpers ----------------------------------------------------
#define SWZ(o) ((o) ^ ((((uint32_t)(o))>>3)&0x70u))

__device__ __forceinline__ uint32_t smem_u32(const void* p){
    return (uint32_t)__cvta_generic_to_shared(p);
}
__device__ __forceinline__ void ldsm4(uint32_t* r, uint32_t a){
    asm volatile("ldmatrix.sync.aligned.m8n8.x4.shared.b16 {%0,%1,%2,%3}, [%4];"
        : "=r"(r[0]), "=r"(r[1]), "=r"(r[2]), "=r"(r[3]) : "r"(a));
}
__device__ __forceinline__ void mma16816(float* d, const uint32_t* a, uint32_t b0, uint32_t b1){
    asm volatile("mma.sync.aligned.m16n8k16.row.col.f32.f16.f16.f32 "
        "{%0,%1,%2,%3}, {%4,%5,%6,%7}, {%8,%9}, {%0,%1,%2,%3};"
        : "+f"(d[0]), "+f"(d[1]), "+f"(d[2]), "+f"(d[3])
        : "r"(a[0]), "r"(a[1]), "r"(a[2]), "r"(a[3]), "r"(b0), "r"(b1));
}
__device__ __forceinline__ void mma16816h(uint32_t* d, const uint32_t* a, uint32_t b0, uint32_t b1){
    asm volatile("mma.sync.aligned.m16n8k16.row.col.f16.f16.f16.f16 "
        "{%0,%1}, {%2,%3,%4,%5}, {%6,%7}, {%0,%1};"
        : "+r"(d[0]), "+r"(d[1])
        : "r"(a[0]), "r"(a[1]), "r"(a[2]), "r"(a[3]), "r"(b0), "r"(b1));
}
__device__ __forceinline__ void cpa16(uint32_t s, const void* g){
    asm volatile("cp.async.cg.shared.global [%0], [%1], 16;" :: "r"(s), "l"(g) : "memory");
}
#define CP_COMMIT() asm volatile("cp.async.commit_group;" ::: "memory")
#define CP_WAIT(n)  asm volatile("cp.async.wait_group %0;" :: "n"(n) : "memory")
__device__ __forceinline__ float rcpf(float x){
    float r; asm("rcp.approx.ftz.f32 %0, %1;" : "=f"(r) : "f"(x)); return r;
}
__device__ __forceinline__ uint32_t ex2h2(uint32_t x){
    uint32_t r; asm("ex2.approx.f16x2 %0, %1;" : "=r"(r) : "r"(x)); return r;
}

// 64x64-half subtile (128B rows): pko; 64x16-half subtile (4 rows/128B): pk16
__device__ __forceinline__ uint32_t pko(int r, int seg){
    return ((uint32_t)(r>>1)<<7) + ((uint32_t)(r&1)<<6) + (uint32_t)seg*16;
}
__device__ __forceinline__ uint32_t pk16(int r, int seg){
    return ((uint32_t)(r>>2)<<7) + ((uint32_t)(r&3)<<5) + (uint32_t)seg*16;
}

// ---------------- prep: convert x; zero accumulators ---------------------------
__global__ void prep_kernel(const float* __restrict__ x){
    int i = blockIdx.x*256 + threadIdx.x;
    float4 v = ((const float4*)x)[i];
    ((__half2*)g_x16)[i*2]   = __floats2half2_rn(v.x, v.y);
    ((__half2*)g_x16)[i*2+1] = __floats2half2_rn(v.z, v.w);
    if (i < B_*L_) g_colw[i] = 0.f;
    if (i < B_*D_) g_t[i] = 0.f;
}

// ---------------- tiled weight transpose (fp32 -> fp16 transposed) -------------
__global__ void transpose_w_kernel(const float* __restrict__ Wq,
                                   const float* __restrict__ Wk){
    __shared__ float t[32][33];
    const float* S = blockIdx.z ? Wk : Wq;
    __half* Dp = blockIdx.z ? g_WkT : g_WqT;
    int bx = blockIdx.x*32, by = blockIdx.y*32;
    int tx = threadIdx.x, ty = threadIdx.y;
#pragma unroll
    for (int i = 0; i < 32; i += 8)
        t[ty+i][tx] = S[(size_t)(by+ty+i)*D_ + bx+tx];
    __syncthreads();
#pragma unroll
    for (int i = 0; i < 32; i += 8)
        Dp[(size_t)(bx+ty+i)*D_ + by+tx] = __float2half(t[tx][ty+i]);
}

// ---------------- generic NT GEMM (HMMA): C[m,n] = sum_k A[m,k] W[n,k] ---------
#define PJ_STAGE 32768
#define PJ_SMEM  (2*PJ_STAGE)

__device__ __forceinline__ void pj_load(const __half* __restrict__ A,
                                        const __half* __restrict__ W,
                                        int m0, int n0, int kc, uint32_t sdst, int tid){
#pragma unroll
    for (int i = 0; i < 8; i++){
        int lin = i*256 + tid;
        int sub = lin >> 9, row = (lin >> 3) & 63, sec = lin & 7;
        const __half* src;
        if (sub < 2) src = A + (size_t)(m0 + sub*64 + row)*D_ + kc + sec*8;
        else         src = W + (size_t)(n0 + (sub-2)*64 + row)*D_ + kc + sec*8;
        cpa16(sdst + sub*8192 + SWZ(row*128 + sec*16), src);
    }
}

__global__ __launch_bounds__(256, 2)
void proj_hmma(const __half* __restrict__ A, const __half* __restrict__ W,
               __half* __restrict__ C){
    extern __shared__ __align__(1024) char sm[];
    const int tid = threadIdx.x, wid = tid >> 5, lane = tid & 31;
    const int m0 = blockIdx.y * 128, n0 = blockIdx.x * 128;
    const uint32_t sb = smem_u32(sm);

    const int mw = (wid & 3) * 32, nw = (wid >> 2) * 64;
    const int a_r = lane & 15, a_s = (lane >> 4) * 16;
    const int b_n = (lane & 7) + ((lane >> 4) << 3);
    const int b_s = ((lane >> 3) & 1) * 16;

    float acc[2][8][4];
#pragma unroll
    for (int i = 0; i < 2; i++)
#pragma unroll
        for (int j = 0; j < 8; j++)
#pragma unroll
            for (int v = 0; v < 4; v++) acc[i][j][v] = 0.f;

    pj_load(A, W, m0, n0, 0, sb, tid); CP_COMMIT();

    for (int c = 0; c < 8; c++){
        if (c < 7){ pj_load(A, W, m0, n0, (c+1)*64, sb + ((c+1)&1)*PJ_STAGE, tid);
                    CP_COMMIT(); CP_WAIT(1); }
        else      { CP_WAIT(0); }
        __syncthreads();
        uint32_t st = sb + (c & 1) * PJ_STAGE;
#pragma unroll
        for (int ks = 0; ks < 4; ks++){
            int kb = ks * 32;
            uint32_t A0[4], A1[4], Bv[4];
            {
                int r0 = mw + a_r, r1 = mw + 16 + a_r;
                ldsm4(A0, st + (r0 >> 6)*8192 + SWZ((r0 & 63)*128 + kb + a_s));
                ldsm4(A1, st + (r1 >> 6)*8192 + SWZ((r1 & 63)*128 + kb + a_s));
            }
#pragma unroll
            for (int nb = 0; nb < 4; nb++){
                int n = nw + nb*16 + b_n;
                ldsm4(Bv, st + (2 + (n >> 6))*8192 + SWZ((n & 63)*128 + kb + b_s));
                mma16816(acc[0][nb*2],   A0, Bv[0], Bv[1]);
                mma16816(acc[0][nb*2+1], A0, Bv[2], Bv[3]);
                mma16816(acc[1][nb*2],   A1, Bv[0], Bv[1]);
                mma16816(acc[1][nb*2+1], A1, Bv[2], Bv[3]);
            }
        }
        __syncthreads();
    }

    const int er = lane >> 2, ec = (lane & 3) * 2;
#pragma unroll
    for (int mt = 0; mt < 2; mt++)
#pragma unroll
        for (int n8 = 0; n8 < 8; n8++){
            size_t r = (size_t)(m0 + mw + mt*16 + er);
            int col = n0 + nw + n8*8 + ec;
            *(__half2*)&C[r*D_ + col] =
                __floats2half2_rn(acc[mt][n8][0], acc[mt][n8][1]);
            *(__half2*)&C[(r+8)*D_ + col] =
                __floats2half2_rn(acc[mt][n8][2], acc[mt][n8][3]);
        }
}

// ---------------- fused scores: fully warp-private, ZERO mainloop barriers -----
// Block 128q x 64k x 4b; warp (b = wid&3, wq = wid>>2) = 64q x 64k fp16 acc.
// kc=16 chunks, 3-deep private buffer ring (32KB/buffer), cp.async groups only.
#define SB_STAGE 32768                       // 16 subtiles x 2KB
#define RED_OFF  (3*SB_STAGE)                // 98304
#define SC_SMEM  (RED_OFF + 1024)            // 99328 -> 2 CTAs/SM
#define PWB 36                               // park words (half2) per q row

// warp-private load: Q subtile (slot wid) + K subtile (slot 8+wid), 8 cpa16
__device__ __forceinline__ void sc_load(const __half* __restrict__ Q,
                                        const __half* __restrict__ K,
                                        int q0, int k0, int kc, uint32_t buf,
                                        int b, int wq, int wid, int lane){
    const __half* qsrc = Q + (size_t)(b*L_ + q0 + wq*64)*D_ + kc;
    uint32_t qdst = buf + wid*2048;
    const __half* ksrc = K + (size_t)(b*L_ + k0)*D_ + kc;
    uint32_t kdst = buf + (8 + wid)*2048;
#pragma unroll
    for (int i = 0; i < 4; i++){
        int idx = i*32 + lane;               // 0..127
        int r = idx >> 1, seg = idx & 1;
        cpa16(qdst + SWZ(pk16(r, seg)), qsrc + (size_t)r*D_ + seg*8);
    }
#pragma unroll
    for (int i = 0; i < 4; i++){
        int idx = i*32 + lane;
        int r = idx >> 1, seg = idx & 1;
        cpa16(kdst + SWZ(pk16(r, seg)), ksrc + (size_t)r*D_ + seg*8);
    }
}

__global__ __launch_bounds__(256, 2)
void scores_hmma(const __half* __restrict__ Q, const __half* __restrict__ K,
                 const int* __restrict__ lens, float* __restrict__ colw){
    extern __shared__ __align__(1024) char sm[];
    const int tid = threadIdx.x, wid = tid >> 5, lane = tid & 31;
    const int q0 = blockIdx.y * 128, k0 = blockIdx.x * 64;
    const uint32_t sb = smem_u32(sm);
    float* red = (float*)(sm + RED_OFF);
    red[tid] = 0.f;

    const int b  = wid & 3;
    const int wq = wid >> 2;
    const int a_r = lane & 15, a_hi = lane >> 4;       // A: row-in-16, seg
    const int b_n = (lane & 7) + ((lane >> 4) << 3);   // B: row-in-16
    const int b_sg = (lane >> 3) & 1;                  // B: seg
    const int er = lane >> 2;

    uint32_t acc[4][8][2];
#pragma unroll
    for (int i = 0; i < 4; i++)
#pragma unroll
        for (int j = 0; j < 8; j++){ acc[i][j][0] = 0u; acc[i][j][1] = 0u; }

    // prologue: prefetch chunks 0,1
    sc_load(Q, K, q0, k0, 0,  sb,             b, wq, wid, lane); CP_COMMIT();
    sc_load(Q, K, q0, k0, 16, sb + SB_STAGE,  b, wq, wid, lane); CP_COMMIT();

    uint32_t buf = sb;                 // buffer of chunk c (ring of 3)
    uint32_t nbuf = sb + 2*SB_STAGE;   // buffer for chunk c+2
    for (int c = 0; c < 32; c++){
        if (c < 30){
            sc_load(Q, K, q0, k0, (c+2)*16, nbuf, b, wq, wid, lane);
            CP_COMMIT();
            CP_WAIT(2);
        } else if (c == 30){ CP_WAIT(1); }
        else               { CP_WAIT(0); }

        uint32_t qt = buf + wid*2048;
        uint32_t kt = buf + (8 + wid)*2048;

        uint32_t Af[4][4];
#pragma unroll
        for (int mt = 0; mt < 4; mt++)
            ldsm4(Af[mt], qt + SWZ(pk16(mt*16 + a_r, a_hi)));
#pragma unroll
        for (int nb = 0; nb < 4; nb++){
            uint32_t Bv[4];
            ldsm4(Bv, kt + SWZ(pk16(nb*16 + b_n, b_sg)));
#pragma unroll
            for (int mt = 0; mt < 4; mt++){
                mma16816h(acc[mt][nb*2],   Af[mt], Bv[0], Bv[1]);
                mma16816h(acc[mt][nb*2+1], Af[mt], Bv[2], Bv[3]);
            }
        }
        // rotate ring: next chunk's buffer, and nbuf advances
        uint32_t t = buf;
        buf  = (buf  == sb + 2*SB_STAGE) ? sb : buf  + SB_STAGE;
        nbuf = t;
    }
    __syncthreads();                         // all warps done; stages -> park

    // ---- park: k-permuted layout, STS.128 ---------------------------------------
    {
        uint32_t* Pw = (uint32_t*)sm;
        const int ecp = lane & 3;
#pragma unroll
        for (int mt = 0; mt < 4; mt++)
#pragma unroll
            for (int rh = 0; rh < 2; rh++){
                int q = wq*64 + mt*16 + rh*8 + er;
                uint32_t w = (uint32_t)(b*4608 + q*PWB + ecp*8);
                *(uint4*)&Pw[w] = make_uint4(acc[mt][0][rh], acc[mt][1][rh],
                                             acc[mt][2][rh], acc[mt][3][rh]);
                *(uint4*)&Pw[w+4] = make_uint4(acc[mt][4][rh], acc[mt][5][rh],
                                               acc[mt][6][rh], acc[mt][7][rh]);
            }
    }
    __syncthreads();

    // ---- batch softmax + masked q reduction (f16x2 exp, fp32 accumulate) --------
    const int le0 = lens[0], le1 = lens[1], le2 = lens[2], le3 = lens[3];
    const uint32_t* Pw = (const uint32_t*)sm;
    const int j = tid & 31;
    const int qg8 = tid >> 5;
    const __half2 C2h = __float2half2_rn(0.09016844f);   // 0.0625*log2(e)
    float2 a0 = {0.f,0.f}, a1 = {0.f,0.f}, a2 = {0.f,0.f}, a3 = {0.f,0.f};
#pragma unroll 4
    for (int it = 0; it < 16; it++){
        int q = it*8 + qg8;
        int base = q*PWB + j;
        uint32_t w0 = Pw[0*4608 + base];
        uint32_t w1 = Pw[1*4608 + base];
        uint32_t w2 = Pw[2*4608 + base];
        uint32_t w3 = Pw[3*4608 + base];
        __half2 e0h = __hmul2(*(__half2*)&w0, C2h);
        __half2 e1h = __hmul2(*(__half2*)&w1, C2h);
        __half2 e2h = __hmul2(*(__half2*)&w2, C2h);
        __half2 e3h = __hmul2(*(__half2*)&w3, C2h);
        uint32_t u0 = ex2h2(*(uint32_t*)&e0h);
        uint32_t u1 = ex2h2(*(uint32_t*)&e1h);
        uint32_t u2 = ex2h2(*(uint32_t*)&e2h);
        uint32_t u3 = ex2h2(*(uint32_t*)&e3h);
        __half2 sum = __hadd2(__hadd2(*(__half2*)&u0, *(__half2*)&u1),
                              __hadd2(*(__half2*)&u2, *(__half2*)&u3));
        float2 sf = __half22float2(sum);
        float ix = rcpf(sf.x), iy = rcpf(sf.y);
        float2 f0 = __half22float2(*(__half2*)&u0);
        float2 f1 = __half22float2(*(__half2*)&u1);
        float2 f2 = __half22float2(*(__half2*)&u2);
        float2 f3 = __half22float2(*(__half2*)&u3);
        int qg = q0 + q;
        if (qg < le0){ a0.x += f0.x*ix; a0.y += f0.y*iy; }
        if (qg < le1){ a1.x += f1.x*ix; a1.y += f1.y*iy; }
        if (qg < le2){ a2.x += f2.x*ix; a2.y += f2.y*iy; }
        if (qg < le3){ a3.x += f3.x*ix; a3.y += f3.y*iy; }
    }
    {
        int ke = (j & 7)*8 + (j >> 3)*2;
        atomicAdd(&red[ke*4 + 0], a0.x); atomicAdd(&red[(ke+1)*4 + 0], a0.y);
        atomicAdd(&red[ke*4 + 1], a1.x); atomicAdd(&red[(ke+1)*4 + 1], a1.y);
        atomicAdd(&red[ke*4 + 2], a2.x); atomicAdd(&red[(ke+1)*4 + 2], a2.y);
        atomicAdd(&red[ke*4 + 3], a3.x); atomicAdd(&red[(ke+1)*4 + 3], a3.y);
    }
    __syncthreads();

    {
        int kl = tid >> 2, bb = tid & 3;
        atomicAdd(&colw[bb*L_ + k0 + kl], red[tid]);
    }
}

// ---------------- tail kernels ----------------------------------------------------
__global__ void colw_x_kernel(){
    int b = blockIdx.x;
    int ks = blockIdx.y * 32;
    int j2 = threadIdx.x;
    const __half2* xb = (const __half2*)(g_x16 + ((size_t)b * L_ + ks) * D_) + j2;
    const float* cw = g_colw + b * L_ + ks;
    float sx = 0.f, sy = 0.f;
#pragma unroll 8
    for (int kk = 0; kk < 32; kk++){
        float2 v = __half22float2(xb[(size_t)kk * 256]);
        float c = cw[kk];
        sx += c * v.x; sy += c * v.y;
    }
    atomicAdd(&g_t[b * D_ + 2*j2],     sx);
    atomicAdd(&g_t[b * D_ + 2*j2 + 1], sy);
}

__global__ void final_kernel(const float* __restrict__ Wv, float* __restrict__ out){
    int warp = (blockIdx.x * blockDim.x + threadIdx.x) >> 5;
    int lane = threadIdx.x & 31;
    int b = warp >> 9;
    int d = warp & 511;
    const float* wr = Wv + (size_t)d * D_;
    const float* tr = g_t + b * D_;
    float s = 0.f;
    for (int j = lane; j < D_; j += 32) s += wr[j] * tr[j];
#pragma unroll
    for (int o = 16; o; o >>= 1) s += __shfl_down_sync(0xffffffffu, s, o);
    if (lane == 0) out[b * D_ + d] = s;
}

// ---------------- launch ------------------------------------------------------------
extern "C" void kernel_launch(void* const* d_in, const int* in_sizes, int n_in,
                              void* d_out, int out_size){
    const float* x   = (const float*)d_in[0];
    const float* Wq  = (const float*)d_in[1];
    const float* Wk  = (const float*)d_in[2];
    const float* Wv  = (const float*)d_in[3];
    const int*  lens = (const int*)d_in[4];
    float* out = (float*)d_out;

    __half *x16, *wqT, *wkT, *hp, *yp;
    float *cwp;
    cudaGetSymbolAddress((void**)&x16, g_x16);
    cudaGetSymbolAddress((void**)&wqT, g_WqT);
    cudaGetSymbolAddress((void**)&wkT, g_WkT);
    cudaGetSymbolAddress((void**)&hp,  g_H);
    cudaGetSymbolAddress((void**)&yp,  g_Y);
    cudaGetSymbolAddress((void**)&cwp, g_colw);

    cudaFuncSetAttribute(proj_hmma,   cudaFuncAttributeMaxDynamicSharedMemorySize, PJ_SMEM);
    cudaFuncSetAttribute(scores_hmma, cudaFuncAttributeMaxDynamicSharedMemorySize, SC_SMEM);

    prep_kernel<<<8192, 256>>>(x);
    transpose_w_kernel<<<dim3(16, 16, 2), dim3(32, 8)>>>(Wq, Wk);

    // H = Wk^T Wq ; Y = x @ H^T ; S = Y x^T
    proj_hmma<<<dim3(4, 4), 256, PJ_SMEM>>>(wkT, wqT, hp);
    proj_hmma<<<dim3(4, 128), 256, PJ_SMEM>>>(x16, hp, yp);

    scores_hmma<<<dim3(64, 32), 256, SC_SMEM>>>(yp, x16, lens, cwp);

    colw_x_kernel<<<dim3(4, 128), 256>>>();
    final_kernel<<<256, 256>>>(Wv, out);
}

// round 15
// speedup vs baseline: 1.2748x; 1.2748x over previous
#include <cuda_runtime.h>
#include <cuda_fp16.h>
#include <stdint.h>

#define B_ 4
#define L_ 4096
#define D_ 512
#define M_ (B_*L_)

// ---------------- device scratch ---------------------------------------------
__device__ __half g_x16[(size_t)M_*D_];
__device__ __half g_WqT[D_*D_], g_WkT[D_*D_];
__device__ __half g_H[D_*D_];
__device__ __half g_Y[(size_t)M_*D_];
__device__ float g_colw[B_*L_];
__device__ float g_t[B_*D_];

// ---------------- helpers ----------------------------------------------------
#define SWZ(o) ((o) ^ ((((uint32_t)(o))>>3)&0x70u))

__device__ __forceinline__ uint32_t smem_u32(const void* p){
    return (uint32_t)__cvta_generic_to_shared(p);
}
__device__ __forceinline__ void ldsm4(uint32_t* r, uint32_t a){
    asm volatile("ldmatrix.sync.aligned.m8n8.x4.shared.b16 {%0,%1,%2,%3}, [%4];"
        : "=r"(r[0]), "=r"(r[1]), "=r"(r[2]), "=r"(r[3]) : "r"(a));
}
__device__ __forceinline__ void mma16816h(uint32_t* d, const uint32_t* a, uint32_t b0, uint32_t b1){
    asm volatile("mma.sync.aligned.m16n8k16.row.col.f16.f16.f16.f16 "
        "{%0,%1}, {%2,%3,%4,%5}, {%6,%7}, {%0,%1};"
        : "+r"(d[0]), "+r"(d[1])
        : "r"(a[0]), "r"(a[1]), "r"(a[2]), "r"(a[3]), "r"(b0), "r"(b1));
}
__device__ __forceinline__ void cpa16(uint32_t s, const void* g){
    asm volatile("cp.async.cg.shared.global [%0], [%1], 16;" :: "r"(s), "l"(g) : "memory");
}
#define CP_COMMIT() asm volatile("cp.async.commit_group;" ::: "memory")
#define CP_WAIT(n)  asm volatile("cp.async.wait_group %0;" :: "n"(n) : "memory")
__device__ __forceinline__ void barp(int id){
    asm volatile("bar.sync %0, 64;" :: "r"(id) : "memory");
}
__device__ __forceinline__ float rcpf(float x){
    float r; asm("rcp.approx.ftz.f32 %0, %1;" : "=f"(r) : "f"(x)); return r;
}
__device__ __forceinline__ uint32_t ex2h2(uint32_t x){
    uint32_t r; asm("ex2.approx.f16x2 %0, %1;" : "=r"(r) : "r"(x)); return r;
}

// packed subtile offset: 64 rows x 32 halfs stored as 32 x 128B smem rows
__device__ __forceinline__ uint32_t pko(int r, int seg){
    return ((uint32_t)(r>>1)<<7) + ((uint32_t)(r&1)<<6) + (uint32_t)seg*16;
}

// ---------------- prep: convert x; transpose-convert Wq,Wk; zero accums --------
__global__ void prep_kernel(const float* __restrict__ x,
                            const float* __restrict__ Wq,
                            const float* __restrict__ Wk){
    int i = blockIdx.x*256 + threadIdx.x;
    float4 v = ((const float4*)x)[i];
    ((__half2*)g_x16)[i*2]   = __floats2half2_rn(v.x, v.y);
    ((__half2*)g_x16)[i*2+1] = __floats2half2_rn(v.z, v.w);
    if (i < D_*D_){
        int r = i >> 9, c = i & 511;
        g_WqT[c*D_ + r] = __float2half(Wq[i]);
        g_WkT[c*D_ + r] = __float2half(Wk[i]);
    }
    if (i < B_*L_) g_colw[i] = 0.f;
    if (i < B_*D_) g_t[i] = 0.f;
}

// ---------------- generic NT GEMM (HMMA fp16-acc): C[m,n] = sum_k A[m,k]W[n,k] -
#define PJ_STAGE 32768
#define PJ_SMEM  (2*PJ_STAGE)

__device__ __forceinline__ void pj_load(const __half* __restrict__ A,
                                        const __half* __restrict__ W,
                                        int m0, int n0, int kc, uint32_t sdst, int tid){
#pragma unroll
    for (int i = 0; i < 8; i++){
        int lin = i*256 + tid;
        int sub = lin >> 9, row = (lin >> 3) & 63, sec = lin & 7;
        const __half* src;
        if (sub < 2) src = A + (size_t)(m0 + sub*64 + row)*D_ + kc + sec*8;
        else         src = W + (size_t)(n0 + (sub-2)*64 + row)*D_ + kc + sec*8;
        cpa16(sdst + sub*8192 + SWZ(row*128 + sec*16), src);
    }
}

__global__ __launch_bounds__(256, 2)
void proj_hmma(const __half* __restrict__ A, const __half* __restrict__ W,
               __half* __restrict__ C){
    extern __shared__ __align__(1024) char sm[];
    const int tid = threadIdx.x, wid = tid >> 5, lane = tid & 31;
    const int m0 = blockIdx.y * 128, n0 = blockIdx.x * 128;
    const uint32_t sb = smem_u32(sm);

    const int mw = (wid & 3) * 32, nw = (wid >> 2) * 64;
    const int a_r = lane & 15, a_s = (lane >> 4) * 16;
    const int b_n = (lane & 7) + ((lane >> 4) << 3);
    const int b_s = ((lane >> 3) & 1) * 16;

    uint32_t acc[2][8][2];                     // fp16x2 accumulators
#pragma unroll
    for (int i = 0; i < 2; i++)
#pragma unroll
        for (int j = 0; j < 8; j++){ acc[i][j][0] = 0u; acc[i][j][1] = 0u; }

    pj_load(A, W, m0, n0, 0, sb, tid); CP_COMMIT();

    for (int c = 0; c < 8; c++){
        if (c < 7){ pj_load(A, W, m0, n0, (c+1)*64, sb + ((c+1)&1)*PJ_STAGE, tid);
                    CP_COMMIT(); CP_WAIT(1); }
        else      { CP_WAIT(0); }
        __syncthreads();
        uint32_t st = sb + (c & 1) * PJ_STAGE;
#pragma unroll
        for (int ks = 0; ks < 4; ks++){
            int kb = ks * 32;
            uint32_t A0[4], A1[4], Bv[4];
            {
                int r0 = mw + a_r, r1 = mw + 16 + a_r;
                ldsm4(A0, st + (r0 >> 6)*8192 + SWZ((r0 & 63)*128 + kb + a_s));
                ldsm4(A1, st + (r1 >> 6)*8192 + SWZ((r1 & 63)*128 + kb + a_s));
            }
#pragma unroll
            for (int nb = 0; nb < 4; nb++){
                int n = nw + nb*16 + b_n;
                ldsm4(Bv, st + (2 + (n >> 6))*8192 + SWZ((n & 63)*128 + kb + b_s));
                mma16816h(acc[0][nb*2],   A0, Bv[0], Bv[1]);
                mma16816h(acc[0][nb*2+1], A0, Bv[2], Bv[3]);
                mma16816h(acc[1][nb*2],   A1, Bv[0], Bv[1]);
                mma16816h(acc[1][nb*2+1], A1, Bv[2], Bv[3]);
            }
        }
        __syncthreads();
    }

    // epilogue: accumulator words ARE the packed half2 outputs
    const int er = lane >> 2, ec = (lane & 3) * 2;
#pragma unroll
    for (int mt = 0; mt < 2; mt++)
#pragma unroll
        for (int n8 = 0; n8 < 8; n8++){
            size_t r = (size_t)(m0 + mw + mt*16 + er);
            int col = n0 + nw + n8*8 + ec;
            *(uint32_t*)&C[r*D_ + col]     = acc[mt][n8][0];
            *(uint32_t*)&C[(r+8)*D_ + col] = acc[mt][n8][1];
        }
}

// ---------------- fused scores (r12, unchanged) --------------------------------
#define ST_STAGE 49152
#define RED_OFF  (2*ST_STAGE)               // 98304
#define SC_SMEM  (RED_OFF + 1024)           // 99328 -> 2 CTAs/SM
#define PWB 36                              // park words (half2) per q row

__device__ __forceinline__ void sc_load_w(const __half* __restrict__ Q,
                                          const __half* __restrict__ K,
                                          int q0, int k0, int kc, uint32_t sdst,
                                          int b, int wq, int lane){
    const __half* qsrc = Q + (size_t)(b*L_ + q0 + wq*64)*D_ + kc;
    uint32_t qdst = sdst + (2*b + wq)*4096;
#pragma unroll
    for (int i = 0; i < 8; i++){
        int idx = i*32 + lane;
        int r = idx >> 2, seg = idx & 3;
        cpa16(qdst + SWZ(pko(r, seg)), qsrc + (size_t)r*D_ + seg*8);
    }
    const __half* ksrc = K + (size_t)(b*L_ + k0 + wq*32)*D_ + kc;
    uint32_t kdst = sdst + (8 + b)*4096;
#pragma unroll
    for (int i = 0; i < 4; i++){
        int idx = i*32 + lane;
        int r = idx >> 2, seg = idx & 3;
        cpa16(kdst + SWZ(pko(r + wq*32, seg)), ksrc + (size_t)r*D_ + seg*8);
    }
}

__global__ __launch_bounds__(256, 2)
void scores_hmma(const __half* __restrict__ Q, const __half* __restrict__ K,
                 const int* __restrict__ lens, float* __restrict__ colw){
    extern __shared__ __align__(1024) char sm[];
    const int tid = threadIdx.x, wid = tid >> 5, lane = tid & 31;
    const int q0 = blockIdx.y * 128, k0 = blockIdx.x * 64;
    const uint32_t sb = smem_u32(sm);
    float* red = (float*)(sm + RED_OFF);
    red[tid] = 0.f;

    const int b  = wid & 3;
    const int wq = wid >> 2;
    const int bar_id = 1 + b;
    const int a_r = lane & 15, a_hi = lane >> 4;
    const int b_n = (lane & 7) + ((lane >> 4) << 3);
    const int b_hi = (lane >> 3) & 1;
    const int er = lane >> 2;

    uint32_t acc[4][8][2];
#pragma unroll
    for (int i = 0; i < 4; i++)
#pragma unroll
        for (int j = 0; j < 8; j++){ acc[i][j][0] = 0u; acc[i][j][1] = 0u; }

    sc_load_w(Q, K, q0, k0, 0, sb, b, wq, lane); CP_COMMIT();

    for (int c = 0; c < 16; c++){
        CP_WAIT(0);
        barp(bar_id);
        if (c < 15){
            sc_load_w(Q, K, q0, k0, (c+1)*32, sb + ((c+1)&1)*ST_STAGE, b, wq, lane);
            CP_COMMIT();
        }
        uint32_t st = sb + (c & 1)*ST_STAGE;
        uint32_t qt = st + (b*2 + wq)*4096;
        uint32_t kt = st + (8 + b)*4096;
#pragma unroll
        for (int ks = 0; ks < 2; ks++){
            uint32_t Af[4][4];
#pragma unroll
            for (int mt = 0; mt < 4; mt++)
                ldsm4(Af[mt], qt + SWZ(pko(mt*16 + a_r, ks*2 + a_hi)));
#pragma unroll
            for (int nb = 0; nb < 4; nb++){
                uint32_t Bv[4];
                ldsm4(Bv, kt + SWZ(pko(nb*16 + b_n, ks*2 + b_hi)));
#pragma unroll
                for (int mt = 0; mt < 4; mt++){
                    mma16816h(acc[mt][nb*2],   Af[mt], Bv[0], Bv[1]);
                    mma16816h(acc[mt][nb*2+1], Af[mt], Bv[2], Bv[3]);
                }
            }
        }
    }
    __syncthreads();                           // stages dead; reuse as park

    // ---- park: k-permuted layout, STS.128 ---------------------------------------
    {
        uint32_t* Pw = (uint32_t*)sm;
        const int ecp = lane & 3;
#pragma unroll
        for (int mt = 0; mt < 4; mt++)
#pragma unroll
            for (int rh = 0; rh < 2; rh++){
                int q = wq*64 + mt*16 + rh*8 + er;
                uint32_t w = (uint32_t)(b*4608 + q*PWB + ecp*8);
                *(uint4*)&Pw[w] = make_uint4(acc[mt][0][rh], acc[mt][1][rh],
                                             acc[mt][2][rh], acc[mt][3][rh]);
                *(uint4*)&Pw[w+4] = make_uint4(acc[mt][4][rh], acc[mt][5][rh],
                                               acc[mt][6][rh], acc[mt][7][rh]);
            }
    }
    __syncthreads();

    // ---- batch softmax + masked q reduction (f16x2 exp, fp32 accumulate) --------
    const int le0 = lens[0], le1 = lens[1], le2 = lens[2], le3 = lens[3];
    const uint32_t* Pw = (const uint32_t*)sm;
    const int j = tid & 31;
    const int qg8 = tid >> 5;
    const __half2 C2h = __float2half2_rn(0.09016844f);   // 0.0625*log2(e)
    float2 a0 = {0.f,0.f}, a1 = {0.f,0.f}, a2 = {0.f,0.f}, a3 = {0.f,0.f};
#pragma unroll 4
    for (int it = 0; it < 16; it++){
        int q = it*8 + qg8;
        int base = q*PWB + j;
        uint32_t w0 = Pw[0*4608 + base];
        uint32_t w1 = Pw[1*4608 + base];
        uint32_t w2 = Pw[2*4608 + base];
        uint32_t w3 = Pw[3*4608 + base];
        __half2 e0h = __hmul2(*(__half2*)&w0, C2h);
        __half2 e1h = __hmul2(*(__half2*)&w1, C2h);
        __half2 e2h = __hmul2(*(__half2*)&w2, C2h);
        __half2 e3h = __hmul2(*(__half2*)&w3, C2h);
        uint32_t u0 = ex2h2(*(uint32_t*)&e0h);
        uint32_t u1 = ex2h2(*(uint32_t*)&e1h);
        uint32_t u2 = ex2h2(*(uint32_t*)&e2h);
        uint32_t u3 = ex2h2(*(uint32_t*)&e3h);
        __half2 sum = __hadd2(__hadd2(*(__half2*)&u0, *(__half2*)&u1),
                              __hadd2(*(__half2*)&u2, *(__half2*)&u3));
        float2 sf = __half22float2(sum);
        float ix = rcpf(sf.x), iy = rcpf(sf.y);
        float2 f0 = __half22float2(*(__half2*)&u0);
        float2 f1 = __half22float2(*(__half2*)&u1);
        float2 f2 = __half22float2(*(__half2*)&u2);
        float2 f3 = __half22float2(*(__half2*)&u3);
        int qg = q0 + q;
        if (qg < le0){ a0.x += f0.x*ix; a0.y += f0.y*iy; }
        if (qg < le1){ a1.x += f1.x*ix; a1.y += f1.y*iy; }
        if (qg < le2){ a2.x += f2.x*ix; a2.y += f2.y*iy; }
        if (qg < le3){ a3.x += f3.x*ix; a3.y += f3.y*iy; }
    }
    {
        int ke = (j & 7)*8 + (j >> 3)*2;
        atomicAdd(&red[ke*4 + 0], a0.x); atomicAdd(&red[(ke+1)*4 + 0], a0.y);
        atomicAdd(&red[ke*4 + 1], a1.x); atomicAdd(&red[(ke+1)*4 + 1], a1.y);
        atomicAdd(&red[ke*4 + 2], a2.x); atomicAdd(&red[(ke+1)*4 + 2], a2.y);
        atomicAdd(&red[ke*4 + 3], a3.x); atomicAdd(&red[(ke+1)*4 + 3], a3.y);
    }
    __syncthreads();

    {
        int kl = tid >> 2, bb = tid & 3;
        atomicAdd(&colw[bb*L_ + k0 + kl], red[tid]);
    }
}

// ---------------- tail kernels ----------------------------------------------------
__global__ void colw_x_kernel(){
    int b = blockIdx.x;
    int ks = blockIdx.y * 32;
    int j2 = threadIdx.x;
    const __half2* xb = (const __half2*)(g_x16 + ((size_t)b * L_ + ks) * D_) + j2;
    const float* cw = g_colw + b * L_ + ks;
    float sx = 0.f, sy = 0.f;
#pragma unroll 8
    for (int kk = 0; kk < 32; kk++){
        float2 v = __half22float2(xb[(size_t)kk * 256]);
        float c = cw[kk];
        sx += c * v.x; sy += c * v.y;
    }
    atomicAdd(&g_t[b * D_ + 2*j2],     sx);
    atomicAdd(&g_t[b * D_ + 2*j2 + 1], sy);
}

__global__ void final_kernel(const float* __restrict__ Wv, float* __restrict__ out){
    int warp = (blockIdx.x * blockDim.x + threadIdx.x) >> 5;
    int lane = threadIdx.x & 31;
    int b = warp >> 9;
    int d = warp & 511;
    const float* wr = Wv + (size_t)d * D_;
    const float* tr = g_t + b * D_;
    float s = 0.f;
    for (int j = lane; j < D_; j += 32) s += wr[j] * tr[j];
#pragma unroll
    for (int o = 16; o; o >>= 1) s += __shfl_down_sync(0xffffffffu, s, o);
    if (lane == 0) out[b * D_ + d] = s;
}

// ---------------- launch ------------------------------------------------------------
extern "C" void kernel_launch(void* const* d_in, const int* in_sizes, int n_in,
                              void* d_out, int out_size){
    const float* x   = (const float*)d_in[0];
    const float* Wq  = (const float*)d_in[1];
    const float* Wk  = (const float*)d_in[2];
    const float* Wv  = (const float*)d_in[3];
    const int*  lens = (const int*)d_in[4];
    float* out = (float*)d_out;

    __half *x16, *wqT, *wkT, *hp, *yp;
    float *cwp;
    cudaGetSymbolAddress((void**)&x16, g_x16);
    cudaGetSymbolAddress((void**)&wqT, g_WqT);
    cudaGetSymbolAddress((void**)&wkT, g_WkT);
    cudaGetSymbolAddress((void**)&hp,  g_H);
    cudaGetSymbolAddress((void**)&yp,  g_Y);
    cudaGetSymbolAddress((void**)&cwp, g_colw);

    cudaFuncSetAttribute(proj_hmma,   cudaFuncAttributeMaxDynamicSharedMemorySize, PJ_SMEM);
    cudaFuncSetAttribute(scores_hmma, cudaFuncAttributeMaxDynamicSharedMemorySize, SC_SMEM);

    prep_kernel<<<8192, 256>>>(x, Wq, Wk);

    // H = Wk^T Wq ; Y = x @ H^T ; S = Y x^T
    proj_hmma<<<dim3(4, 4), 256, PJ_SMEM>>>(wkT, wqT, hp);
    proj_hmma<<<dim3(4, 128), 256, PJ_SMEM>>>(x16, hp, yp);

    scores_hmma<<<dim3(64, 32), 256, SC_SMEM>>>(yp, x16, lens, cwp);

    colw_x_kernel<<<dim3(4, 128), 256>>>();
    final_kernel<<<256, 256>>>(Wv, out);
}